// round 10
// baseline (speedup 1.0000x reference)
#include <cuda_runtime.h>
#include <cuda_bf16.h>

#define TPB 256
#define RPT 4          // anchors per thread (R6 champion config)
#define MAXA 256       // smem GT capacity (A=64 here, +1 sentinel)

__global__ __launch_bounds__(TPB)
void AssignClsLabel_kernel(const float4* __restrict__ anchors,
                           const float4* __restrict__ gts,
                           const int* __restrict__ counts,
                           const int* __restrict__ use_anchor_p,
                           float* __restrict__ out,
                           int N, int A, int blocksPerBatch) {
    // GT record: (gy2, -gy1, gx2, -gx1) + scalar -(2/3)*ga
    __shared__ float4 sgc[MAXA + 1];
    __shared__ float  sgn[MAXA + 1];
    __shared__ float  sredmax[TPB / 32], sredmin[TPB / 32];
    __shared__ int    scnt;

    const int b   = blockIdx.x / blocksPerBatch;     // linear mapping (R6)
    const int blk = blockIdx.x - b * blocksPerBatch;
    const int cnt = counts[b];
    const int ua  = use_anchor_p ? use_anchor_p[0] : 1;
    const int tid = threadIdx.x;
    const int base = blk * (TPB * RPT) + tid;

    // ---- Load anchors; precompute corners (y1,x1 negated) + areas ----
    float y2v[RPT], y1n[RPT], x2v[RPT], x1n[RPT], ar[RPT], wm[RPT];
    float amax = -1e30f, amin = 1e30f;
    #pragma unroll
    for (int r = 0; r < RPT; r++) {
        int idx = base + r * TPB;
        // OOB sentinel: y2v huge, y1n very negative -> dy3 = gy2 - gy1 > 0,
        // but x2v=-8e9 -> dx <= x2+(-gx1) < 0 -> w <= -(2/3)ga < thr-band. Label 0.
        y2v[r] = 4e9f; y1n[r] = -4.1e9f; x2v[r] = -8e9f; x1n[r] = -8e9f; ar[r] = 1.f;
        wm[r] = -1e30f;
        if (idx < N) {
            float4 a = anchors[(size_t)b * N + idx];
            float y1, y2, x1, x2;
            if (ua) {
                y1 = a.x - 0.5f * a.z;  y2 = y1 + a.z;
                x1 = a.y - 0.5f * a.w;  x2 = x1 + a.w;
                ar[r] = __fmul_rn(a.z, a.w);
            } else {
                y1 = a.x; x1 = a.y; y2 = a.z; x2 = a.w;
                ar[r] = __fmul_rn(__fsub_rn(y2, y1), __fsub_rn(x2, x1));
            }
            y2v[r] = y2;  y1n[r] = -y1;
            x2v[r] = x2;  x1n[r] = -x1;
            amax = fmaxf(amax, ar[r]);
            amin = fminf(amin, ar[r]);
        }
    }

    // ---- Block-wide anchor-area min/max for exact GT pruning ----
    #pragma unroll
    for (int off = 16; off > 0; off >>= 1) {
        amax = fmaxf(amax, __shfl_xor_sync(0xffffffffu, amax, off));
        amin = fminf(amin, __shfl_xor_sync(0xffffffffu, amin, off));
    }
    if ((tid & 31) == 0) { sredmax[tid >> 5] = amax; sredmin[tid >> 5] = amin; }
    if (tid == 0) scnt = 0;
    __syncthreads();
    amax = sredmax[0]; amin = sredmin[0];
    #pragma unroll
    for (int w = 1; w < TPB / 32; w++) {
        amax = fmaxf(amax, sredmax[w]);
        amin = fminf(amin, sredmin[w]);
    }
    // iou>=0.5 requires area/2 <= ga <= 2*area; 0.5% slack >> fp rounding,
    // so the prune only removes provably-unmatchable GTs (labels unchanged).
    const float gaHi = 2.01f * amax;
    const float gaLo = amin * (1.0f / 2.01f);

    // ---- Stage + compact matchable GTs ----
    for (int g = tid; g < cnt; g += TPB) {
        float4 v = gts[(size_t)b * A + g];           // (gy1, gx1, gy2, gx2)
        float ga = __fmul_rn(__fsub_rn(v.z, v.x), __fsub_rn(v.w, v.y));
        if (ga <= gaHi && ga >= gaLo) {
            int p = atomicAdd(&scnt, 1);
            sgc[p] = make_float4(v.z, -v.x, v.w, -v.y);
            sgn[p] = -0.66666668653488159f * ga;     // -(2/3)*ga (rounded; band covers)
        }
    }
    __syncthreads();
    const int m = scnt;
    if (m > 0 && tid == 0) { sgc[m] = sgc[0]; sgn[m] = sgn[0]; }   // prefetch sentinel
    __syncthreads();

    // ---- Main loop: 9 slots/pair (5 alu FMNMX/FMAX + 4 fma-pipe FADD/FFMA) ----
    //   dy3  = min(y2,gy2) + min(-y1,-gy1)     ( = min(y2,gy2) - max(y1,gy1) )
    //   dypp = dy3 + |dy3|  = 2*max(dy3,0)     (exact; |.| is a free modifier)
    //   dx   = min(x2,gx2) + min(-x1,-gx1)     (unclamped: dx<0 => w < thr-band)
    //   w    = fma(dypp, dx, -(2/3)ga)  ~ 2*inter - (2/3)ga ;  label+ test: w >= (2/3)ar
    float4 gc = sgc[0];
    float  gn = sgn[0];
    #pragma unroll 2
    for (int g = 0; g < m; g++) {
        const float4 gcc = gc;
        const float  gnc = gn;
        gc = sgc[g + 1]; gn = sgn[g + 1];            // unconditional (sentinel)
        #pragma unroll
        for (int r = 0; r < RPT; r++) {
            float dy3  = __fadd_rn(fminf(y2v[r], gcc.x), fminf(y1n[r], gcc.y));
            float dypp = __fadd_rn(dy3, fabsf(dy3));            // 2*max(dy3,0)
            float dx   = __fadd_rn(fminf(x2v[r], gcc.z), fminf(x1n[r], gcc.w));
            float w    = __fmaf_rn(dypp, dx, gnc);
            wm[r] = fmaxf(wm[r], w);
        }
    }

    // ---- Classify; band hits (rare) -> literal bit-exact fallback ----
    #pragma unroll
    for (int r = 0; r < RPT; r++) {
        int idx = base + r * TPB;
        if (idx >= N) continue;
        float thr  = 0.66666668653488159f * ar[r];
        // band = 2e-5*(ar+gaHi): >=50x fast-path rounding + threshold-fold slack.
        float band = 2e-5f * (ar[r] + gaHi);
        float lab;
        if (wm[r] >= thr + band) {
            lab = 1.0f;
        } else if (wm[r] <= thr - band) {
            lab = 0.0f;
        } else {
            // Exact literal reference replay for this anchor.
            lab = 0.0f;
            float4 a = anchors[(size_t)b * N + idx];
            float y1, y2, x1, x2, area;
            if (ua) {
                y1 = a.x - 0.5f * a.z;  y2 = y1 + a.z;
                x1 = a.y - 0.5f * a.w;  x2 = x1 + a.w;
                area = __fmul_rn(a.z, a.w);
            } else {
                y1 = a.x; x1 = a.y; y2 = a.z; x2 = a.w;
                area = __fmul_rn(__fsub_rn(y2, y1), __fsub_rn(x2, x1));
            }
            for (int g = 0; g < cnt; g++) {
                float4 v2 = gts[(size_t)b * A + g];
                float ga2 = __fmul_rn(__fsub_rn(v2.z, v2.x), __fsub_rn(v2.w, v2.y));
                float yy1 = fminf(fmaxf(y1, v2.x), v2.z);
                float yy2 = fminf(fmaxf(y2, v2.x), v2.z);
                float xx1 = fminf(fmaxf(x1, v2.y), v2.w);
                float xx2 = fminf(fmaxf(x2, v2.y), v2.w);
                float it  = __fmul_rn(__fsub_rn(yy2, yy1), __fsub_rn(xx2, xx1));
                float uni = __fsub_rn(__fadd_rn(area, ga2), it);
                if (__fdiv_rn(it, uni) >= 0.5f) { lab = 1.0f; break; }
            }
        }
        out[(size_t)b * N + idx] = lab;
    }
}

extern "C" void kernel_launch(void* const* d_in, const int* in_sizes, int n_in,
                              void* d_out, int out_size) {
    // Bind by size signature: anchors = largest; gts = 2nd largest;
    // of the rest, counts = larger (B elems), use_anchor = smaller (optional).
    int ia = 0;
    for (int i = 1; i < n_in; i++) if (in_sizes[i] > in_sizes[ia]) ia = i;
    int ig = -1;
    for (int i = 0; i < n_in; i++) {
        if (i == ia) continue;
        if (ig < 0 || in_sizes[i] > in_sizes[ig]) ig = i;
    }
    int ic = -1, iu = -1;
    for (int i = 0; i < n_in; i++) {
        if (i == ia || i == ig) continue;
        if (ic < 0) ic = i;
        else if (in_sizes[i] > in_sizes[ic]) { iu = ic; ic = i; }
        else iu = i;
    }

    const float4* anchors = (const float4*)d_in[ia];
    const float4* gts     = (const float4*)d_in[ig];
    const int*    counts  = (const int*)d_in[ic];
    const int*    ua_ptr  = (iu >= 0) ? (const int*)d_in[iu] : (const int*)0;
    float* out = (float*)d_out;

    const int B = in_sizes[ic];
    const int A = in_sizes[ig] / (4 * B);
    const int N = in_sizes[ia] / (4 * B);

    const int anchorsPerBlock = TPB * RPT;
    const int blocksPerBatch = (N + anchorsPerBlock - 1) / anchorsPerBlock;
    const int grid = B * blocksPerBatch;

    AssignClsLabel_kernel<<<grid, TPB>>>(anchors, gts, counts, ua_ptr, out,
                                         N, A, blocksPerBatch);
}